// round 1
// baseline (speedup 1.0000x reference)
#include <cuda_runtime.h>
#include <cfloat>
#include <math.h>

#define FULL 0xffffffffu

constexpr int B = 4;
constexpr int N = 8192;
constexpr int M = 4096;
constexpr int F = 64;
constexpr int K = 16;
constexpr float MIN_SIGMA = 1e-4f;

// Scratch: features transposed to (B, N, F) so a point's 64 features are one
// contiguous 256B row (coalesced float2 loads across the warp). 8MB.
__device__ float g_featT[(size_t)B * N * F];

// ---------------------------------------------------------------------------
// Prep: transpose point_features (B, F, N) -> g_featT (B, N, F)
// ---------------------------------------------------------------------------
__global__ void transpose_feat_kernel(const float* __restrict__ feat) {
    __shared__ float tile[32][33];
    const int b  = blockIdx.z;
    const int n0 = blockIdx.x * 32;
    const int f0 = blockIdx.y * 32;
    const int tx = threadIdx.x, ty = threadIdx.y;

    // read feat[b][f0+i][n0+tx]  (coalesced over tx)
    #pragma unroll
    for (int i = ty; i < 32; i += 8)
        tile[i][tx] = feat[(size_t)b * F * N + (size_t)(f0 + i) * N + (n0 + tx)];
    __syncthreads();
    // write featT[b][n0+i][f0+tx] (coalesced over tx)
    #pragma unroll
    for (int i = ty; i < 32; i += 8)
        g_featT[((size_t)b * N + (n0 + i)) * F + (f0 + tx)] = tile[tx][i];
}

// ---------------------------------------------------------------------------
// Warp-cooperative top-K insert. Sorted ascending list distributed over
// lanes 0..K-1 (lane l = l-th smallest). threshold = current K-th value
// (warp-uniform). Candidates processed in increasing point index order so
// tie behavior matches jax.lax.top_k (first occurrence wins).
// ---------------------------------------------------------------------------
__device__ __forceinline__ void topk_insert(float s, int pidx, int lane,
                                            float& val, int& idx,
                                            float& threshold) {
    unsigned bal = __ballot_sync(FULL, s < threshold);
    while (bal) {
        const int src = __ffs(bal) - 1;
        bal &= bal - 1;
        const float cs = __shfl_sync(FULL, s, src);
        if (cs < threshold) {  // warp-uniform; threshold may have shrunk
            const int ci = __shfl_sync(FULL, pidx, src);
            const unsigned less = __ballot_sync(FULL, (lane < K) && (val <= cs));
            const int pp = __popc(less);            // insertion position
            const float ot = __shfl_up_sync(FULL, val, 1);
            const int   oi = __shfl_up_sync(FULL, idx, 1);
            if (lane < K) {
                if (lane == pp)     { val = cs; idx = ci; }
                else if (lane > pp) { val = ot; idx = oi; }
            }
            threshold = __shfl_sync(FULL, val, K - 1);
        }
    }
}

// ---------------------------------------------------------------------------
// Main kernel: one warp per query. Point cloud for the batch lives in SMEM
// as float4 {x, y, z, 0.5*|p|^2}. Surrogate score s = 0.5|p|^2 - q.p is
// monotone in squared distance (q^2 is constant per query and cancels in the
// softmax: d2 - d2min = 2*(s - s_min)).
// ---------------------------------------------------------------------------
__global__ void __launch_bounds__(512, 1)
soft_projection_kernel(const float* __restrict__ pc,
                       const float* __restrict__ qc,
                       const float* __restrict__ temp,
                       float* __restrict__ out) {
    extern __shared__ float4 spts[];  // N * 16B = 128KB

    const int b = blockIdx.y;
    const float* pcb = pc + (size_t)b * 3 * N;

    // Cooperative SMEM fill (coalesced reads of x/y/z planes)
    for (int n = threadIdx.x; n < N; n += blockDim.x) {
        const float x = pcb[n];
        const float y = pcb[N + n];
        const float z = pcb[2 * N + n];
        spts[n] = make_float4(x, y, z, 0.5f * (x * x + y * y + z * z));
    }
    __syncthreads();

    const float t = *temp;
    const float sigma = fmaxf(t * t, MIN_SIGMA);
    const float inv_sigma2 = 2.0f / sigma;  // d2-delta = 2*(s - s0)

    const int lane = threadIdx.x & 31;
    const int warp = threadIdx.x >> 5;
    const int nw = blockDim.x >> 5;                 // 16 warps
    const int wg = blockIdx.x * nw + warp;          // warp id within batch
    const int wstride = gridDim.x * nw;             // 592

    const float* qcb = qc + (size_t)b * 3 * M;
    float* out_pts  = out + (size_t)b * 3 * M;
    float* out_feat = out + (size_t)B * 3 * M + (size_t)b * F * M;
    const float* featb = g_featT + (size_t)b * N * F;

    for (int m = wg; m < M; m += wstride) {
        const float qx = qcb[m];
        const float qy = qcb[M + m];
        const float qz = qcb[2 * M + m];

        float val = FLT_MAX;     // lane-held top-K entry (lanes 0..K-1)
        int   idx = 0;
        float threshold = FLT_MAX;

        // Scan all points, 4 per lane per step (128 points per warp-step).
        // One combined vote in the common no-candidate case.
        for (int n = lane; n < N; n += 128) {
            const float4 p0 = spts[n];
            const float4 p1 = spts[n + 32];
            const float4 p2 = spts[n + 64];
            const float4 p3 = spts[n + 96];
            const float s0 = fmaf(-qz, p0.z, fmaf(-qy, p0.y, fmaf(-qx, p0.x, p0.w)));
            const float s1 = fmaf(-qz, p1.z, fmaf(-qy, p1.y, fmaf(-qx, p1.x, p1.w)));
            const float s2 = fmaf(-qz, p2.z, fmaf(-qy, p2.y, fmaf(-qx, p2.x, p2.w)));
            const float s3 = fmaf(-qz, p3.z, fmaf(-qy, p3.y, fmaf(-qx, p3.x, p3.w)));
            const float smin = fminf(fminf(s0, s1), fminf(s2, s3));
            if (__any_sync(FULL, smin < threshold)) {
                topk_insert(s0, n,      lane, val, idx, threshold);
                topk_insert(s1, n + 32, lane, val, idx, threshold);
                topk_insert(s2, n + 64, lane, val, idx, threshold);
                topk_insert(s3, n + 96, lane, val, idx, threshold);
            }
        }

        // --- softmax weights over the K selected (lanes 0..K-1, sorted) ---
        const float s_min = __shfl_sync(FULL, val, 0);
        const float e = (lane < K) ? __expf(-(val - s_min) * inv_sigma2) : 0.0f;
        float esum = e;
        #pragma unroll
        for (int o = 16; o; o >>= 1) esum += __shfl_xor_sync(FULL, esum, o);
        const float w = e / esum;

        // --- projected points: sum_k w_k * p_k ---
        float wx = 0.f, wy = 0.f, wz = 0.f;
        if (lane < K) {
            const float4 gp = spts[idx];
            wx = w * gp.x; wy = w * gp.y; wz = w * gp.z;
        }
        #pragma unroll
        for (int o = 16; o; o >>= 1) {
            wx += __shfl_xor_sync(FULL, wx, o);
            wy += __shfl_xor_sync(FULL, wy, o);
            wz += __shfl_xor_sync(FULL, wz, o);
        }
        if (lane == 0) {
            out_pts[m]         = wx;
            out_pts[M + m]     = wy;
            out_pts[2 * M + m] = wz;
        }

        // --- propagated features: each lane owns 2 feature channels ---
        float a0 = 0.f, a1 = 0.f;
        #pragma unroll
        for (int j = 0; j < K; j++) {
            const float wj = __shfl_sync(FULL, w, j);
            const int   gj = __shfl_sync(FULL, idx, j);
            const float2 f2 = *reinterpret_cast<const float2*>(
                featb + (size_t)gj * F + lane * 2);
            a0 = fmaf(wj, f2.x, a0);
            a1 = fmaf(wj, f2.y, a1);
        }
        out_feat[(size_t)(2 * lane) * M + m]     = a0;
        out_feat[(size_t)(2 * lane + 1) * M + m] = a1;
    }
}

// ---------------------------------------------------------------------------
extern "C" void kernel_launch(void* const* d_in, const int* in_sizes, int n_in,
                              void* d_out, int out_size) {
    const float* pc   = (const float*)d_in[0];  // (B,3,N)
    const float* qc   = (const float*)d_in[1];  // (B,3,M)
    const float* pf   = (const float*)d_in[2];  // (B,F,N)
    const float* temp = (const float*)d_in[3];  // scalar
    float* out = (float*)d_out;                 // (B,3,M) ++ (B,F,M)

    (void)in_sizes; (void)n_in; (void)out_size;

    // 128KB dynamic SMEM needs an opt-in (runs only during graph capture).
    cudaFuncSetAttribute(soft_projection_kernel,
                         cudaFuncAttributeMaxDynamicSharedMemorySize,
                         N * (int)sizeof(float4));

    transpose_feat_kernel<<<dim3(N / 32, F / 32, B), dim3(32, 8)>>>(pf);
    soft_projection_kernel<<<dim3(37, B), 512, N * sizeof(float4)>>>(pc, qc, temp, out);
}

// round 2
// speedup vs baseline: 1.3060x; 1.3060x over previous
#include <cuda_runtime.h>
#include <cfloat>
#include <math.h>

#define FULL 0xffffffffu

constexpr int B = 4;
constexpr int N = 8192;
constexpr int M = 4096;
constexpr int F = 64;
constexpr int K = 16;
constexpr float MIN_SIGMA = 1e-4f;

// Scratch: features transposed to (B, N, F) so a point's 64 features are one
// contiguous 256B row (coalesced float2 loads across the warp). 8MB.
__device__ float g_featT[(size_t)B * N * F];

// ---------------------------------------------------------------------------
// Prep: transpose point_features (B, F, N) -> g_featT (B, N, F)
// ---------------------------------------------------------------------------
__global__ void transpose_feat_kernel(const float* __restrict__ feat) {
    __shared__ float tile[32][33];
    const int b  = blockIdx.z;
    const int n0 = blockIdx.x * 32;
    const int f0 = blockIdx.y * 32;
    const int tx = threadIdx.x, ty = threadIdx.y;

    #pragma unroll
    for (int i = ty; i < 32; i += 8)
        tile[i][tx] = feat[(size_t)b * F * N + (size_t)(f0 + i) * N + (n0 + tx)];
    __syncthreads();
    #pragma unroll
    for (int i = ty; i < 32; i += 8)
        g_featT[((size_t)b * N + (n0 + i)) * F + (f0 + tx)] = tile[tx][i];
}

// ---------------------------------------------------------------------------
// Warp-cooperative top-K insert into a 16-entry sorted list held in lanes
// [base, base+16). Candidates may come from any of the 32 lanes.
// threshold = current K-th (largest kept) value, warp-uniform.
// Candidates processed in increasing point-index order -> jax.lax.top_k tie
// semantics (first occurrence wins) via stable (val <= cs) positioning.
// ---------------------------------------------------------------------------
__device__ __forceinline__ void topk_insert(float s, int pidx, int lane,
                                            float& val, int& idx,
                                            float& threshold, int base) {
    unsigned bal = __ballot_sync(FULL, s < threshold);
    while (bal) {
        const int src = __ffs(bal) - 1;
        bal &= bal - 1;
        const float cs = __shfl_sync(FULL, s, src);
        if (cs < threshold) {  // warp-uniform; threshold may have shrunk
            const int ci = __shfl_sync(FULL, pidx, src);
            const bool mine = (unsigned)(lane - base) < (unsigned)K;
            const unsigned less = __ballot_sync(FULL, mine && (val <= cs));
            const int pos = base + __popc(less);     // insertion lane
            const float ot = __shfl_up_sync(FULL, val, 1);
            const int   oi = __shfl_up_sync(FULL, idx, 1);
            if (mine) {
                if (lane == pos)     { val = cs; idx = ci; }
                else if (lane > pos) { val = ot; idx = oi; }
            }
            threshold = __shfl_sync(FULL, val, base + K - 1);
        }
    }
}

// ---------------------------------------------------------------------------
// Main kernel: one warp handles TWO queries. Point cloud in SMEM as
// float4 {x, y, z, 0.5*|p|^2}; each LDS.128 feeds both queries' scores.
// Surrogate s = 0.5|p|^2 - q.p is monotone in d^2; q^2 cancels in softmax
// (d2 - d2min = 2*(s - s_min)).
// Query A's top-16 lives in lanes 0..15, query B's in lanes 16..31.
// ---------------------------------------------------------------------------
__global__ void __launch_bounds__(1024, 1)
soft_projection_kernel(const float* __restrict__ pc,
                       const float* __restrict__ qc,
                       const float* __restrict__ temp,
                       float* __restrict__ out) {
    extern __shared__ float4 spts[];  // N * 16B = 128KB

    const int b = blockIdx.y;
    const float* pcb = pc + (size_t)b * 3 * N;

    for (int n = threadIdx.x; n < N; n += blockDim.x) {
        const float x = pcb[n];
        const float y = pcb[N + n];
        const float z = pcb[2 * N + n];
        spts[n] = make_float4(x, y, z, 0.5f * (x * x + y * y + z * z));
    }
    __syncthreads();

    const float t = *temp;
    const float sigma = fmaxf(t * t, MIN_SIGMA);
    const float inv_sigma2 = 2.0f / sigma;

    const int lane = threadIdx.x & 31;
    const int warp = threadIdx.x >> 5;
    const int nw = blockDim.x >> 5;                 // 32 warps
    const int wg = blockIdx.x * nw + warp;
    const int wstride = gridDim.x * nw;             // 37*32 = 1184

    const float* qcb = qc + (size_t)b * 3 * M;
    float* out_pts  = out + (size_t)b * 3 * M;
    float* out_feat = out + (size_t)B * 3 * M + (size_t)b * F * M;
    const float* featb = g_featT + (size_t)b * N * F;

    for (int task = wg; task < M / 2; task += wstride) {
        const int m0 = 2 * task;
        const int m1 = 2 * task + 1;

        const float ax = qcb[m0],         bx = qcb[m1];
        const float ay = qcb[M + m0],     by = qcb[M + m1];
        const float az = qcb[2 * M + m0], bz = qcb[2 * M + m1];

        float val = FLT_MAX;   // lane-held list entry (half-warp per query)
        int   idx = 0;
        float th0 = FLT_MAX;   // query A threshold (warp-uniform)
        float th1 = FLT_MAX;   // query B threshold (warp-uniform)

        // Scan: 2 points per lane per step (64 points/warp-step), each point
        // scored for both queries. One combined vote on the fast path.
        for (int n = lane; n < N; n += 64) {
            const float4 p0 = spts[n];
            const float4 p1 = spts[n + 32];
            const float sa0 = fmaf(-az, p0.z, fmaf(-ay, p0.y, fmaf(-ax, p0.x, p0.w)));
            const float sa1 = fmaf(-az, p1.z, fmaf(-ay, p1.y, fmaf(-ax, p1.x, p1.w)));
            const float sb0 = fmaf(-bz, p0.z, fmaf(-by, p0.y, fmaf(-bx, p0.x, p0.w)));
            const float sb1 = fmaf(-bz, p1.z, fmaf(-by, p1.y, fmaf(-bx, p1.x, p1.w)));
            const bool c = (fminf(sa0, sa1) < th0) | (fminf(sb0, sb1) < th1);
            if (__any_sync(FULL, c)) {
                topk_insert(sa0, n,      lane, val, idx, th0, 0);
                topk_insert(sa1, n + 32, lane, val, idx, th0, 0);
                topk_insert(sb0, n,      lane, val, idx, th1, 16);
                topk_insert(sb1, n + 32, lane, val, idx, th1, 16);
            }
        }

        // --- softmax over each half-warp's sorted list ---
        const int base = lane & 16;                       // 0 for A, 16 for B
        const float s_min = __shfl_sync(FULL, val, base); // per-half min
        const float e = __expf(-(val - s_min) * inv_sigma2);
        float esum = e;
        #pragma unroll
        for (int o = 8; o; o >>= 1) esum += __shfl_xor_sync(FULL, esum, o);
        const float w = e / esum;

        // --- projected points (per-half reduction) ---
        const float4 gp = spts[idx];
        float wx = w * gp.x, wy = w * gp.y, wz = w * gp.z;
        #pragma unroll
        for (int o = 8; o; o >>= 1) {
            wx += __shfl_xor_sync(FULL, wx, o);
            wy += __shfl_xor_sync(FULL, wy, o);
            wz += __shfl_xor_sync(FULL, wz, o);
        }
        if (lane == 0) {
            out_pts[m0]         = wx;
            out_pts[M + m0]     = wy;
            out_pts[2 * M + m0] = wz;
        } else if (lane == 16) {
            out_pts[m1]         = wx;
            out_pts[M + m1]     = wy;
            out_pts[2 * M + m1] = wz;
        }

        // --- propagated features: all 32 lanes per query, 2 channels/lane ---
        {
            float a0 = 0.f, a1 = 0.f, b0 = 0.f, b1 = 0.f;
            #pragma unroll
            for (int j = 0; j < K; j++) {
                const float wj = __shfl_sync(FULL, w, j);
                const int   gj = __shfl_sync(FULL, idx, j);
                const float2 f2 = *reinterpret_cast<const float2*>(
                    featb + (size_t)gj * F + lane * 2);
                a0 = fmaf(wj, f2.x, a0);
                a1 = fmaf(wj, f2.y, a1);
            }
            #pragma unroll
            for (int j = K; j < 2 * K; j++) {
                const float wj = __shfl_sync(FULL, w, j);
                const int   gj = __shfl_sync(FULL, idx, j);
                const float2 f2 = *reinterpret_cast<const float2*>(
                    featb + (size_t)gj * F + lane * 2);
                b0 = fmaf(wj, f2.x, b0);
                b1 = fmaf(wj, f2.y, b1);
            }
            out_feat[(size_t)(2 * lane) * M + m0]     = a0;
            out_feat[(size_t)(2 * lane + 1) * M + m0] = a1;
            out_feat[(size_t)(2 * lane) * M + m1]     = b0;
            out_feat[(size_t)(2 * lane + 1) * M + m1] = b1;
        }
    }
}

// ---------------------------------------------------------------------------
extern "C" void kernel_launch(void* const* d_in, const int* in_sizes, int n_in,
                              void* d_out, int out_size) {
    const float* pc   = (const float*)d_in[0];  // (B,3,N)
    const float* qc   = (const float*)d_in[1];  // (B,3,M)
    const float* pf   = (const float*)d_in[2];  // (B,F,N)
    const float* temp = (const float*)d_in[3];  // scalar
    float* out = (float*)d_out;                 // (B,3,M) ++ (B,F,M)

    (void)in_sizes; (void)n_in; (void)out_size;

    cudaFuncSetAttribute(soft_projection_kernel,
                         cudaFuncAttributeMaxDynamicSharedMemorySize,
                         N * (int)sizeof(float4));

    transpose_feat_kernel<<<dim3(N / 32, F / 32, B), dim3(32, 8)>>>(pf);
    soft_projection_kernel<<<dim3(37, B), 1024, N * sizeof(float4)>>>(pc, qc, temp, out);
}